// round 12
// baseline (speedup 1.0000x reference)
#include <cuda_runtime.h>
#include <cuda_fp16.h>
#include <math.h>
#include <stdint.h>

// Problem constants
#define HW     36864          // 192*192
#define CIN    64
#define BS     2
#define NQ     4096
#define COUT   69

// Tiling
#define QT     128            // queries per block
#define CK     64             // m per chunk
#define NSEG   21             // grid 7*21*2 = 294 <= 148*occ2 = 296 (single wave)
#define TCH    (HW / CK)      // 576 total chunks
#define MAXV   896            // 7 * 128 slots
#define PSTR   144            // V shared row stride bytes (72 fp16)
#define NCH    72             // V rows: 64 fea + 3 sq + 3 nrm + ones + zero
#define VROWS  72
#define VSZ    (VROWS * PSTR)

struct QParam {
    int nv;
    int rowstart[65];
    int umin[64];
};

// Split-K partials
__device__ __align__(16) float g_acc[BS][NSEG][MAXV][NCH];

// ---------------- PTX helpers ----------------
#define FMA2(d, a, b, c) asm("fma.rn.f32x2 %0, %1, %2, %3;" : "=l"(d) : "l"(a), "l"(b), "l"(c))

__device__ __forceinline__ uint32_t smem_u32(const void* p) {
    uint32_t a;
    asm("{ .reg .u64 t; cvta.to.shared.u64 t, %1; cvt.u32.u64 %0, t; }"
        : "=r"(a) : "l"(p));
    return a;
}
__device__ __forceinline__ unsigned long long pk2(float lo, float hi) {
    unsigned long long r;
    asm("mov.b64 %0, {%1, %2};" : "=l"(r) : "f"(lo), "f"(hi));
    return r;
}
__device__ __forceinline__ void upk2(unsigned long long v, float& lo, float& hi) {
    asm("mov.b64 {%0, %1}, %2;" : "=f"(lo), "=f"(hi) : "l"(v));
}
__device__ __forceinline__ uint32_t cvt_f16x2(float lo, float hi) {
    uint32_t r; asm("cvt.rn.f16x2.f32 %0, %1, %2;" : "=r"(r) : "f"(hi), "f"(lo)); return r;
}
__device__ __forceinline__ uint32_t ex2_f16x2(uint32_t a) {
    uint32_t r; asm("ex2.approx.f16x2 %0, %1;" : "=r"(r) : "r"(a)); return r;
}
__device__ __forceinline__ uint32_t mul_f16x2(uint32_t a, uint32_t b) {
    uint32_t r; asm("mul.rn.f16x2 %0, %1, %2;" : "=r"(r) : "r"(a), "r"(b)); return r;
}
__device__ __forceinline__ void ldsm_x4(uint32_t& r0, uint32_t& r1, uint32_t& r2,
                                        uint32_t& r3, uint32_t addr) {
    asm volatile("ldmatrix.sync.aligned.m8n8.x4.shared.b16 {%0,%1,%2,%3}, [%4];"
                 : "=r"(r0), "=r"(r1), "=r"(r2), "=r"(r3) : "r"(addr));
}
__device__ __forceinline__ void ldsm_x2(uint32_t& r0, uint32_t& r1, uint32_t addr) {
    asm volatile("ldmatrix.sync.aligned.m8n8.x2.shared.b16 {%0,%1}, [%2];"
                 : "=r"(r0), "=r"(r1) : "r"(addr));
}
__device__ __forceinline__ void mma16816(float* d, const uint32_t* a,
                                         uint32_t b0, uint32_t b1) {
    asm volatile("mma.sync.aligned.m16n8k16.row.col.f32.f16.f16.f32 "
                 "{%0,%1,%2,%3}, {%4,%5,%6,%7}, {%8,%9}, {%0,%1,%2,%3};"
                 : "+f"(d[0]), "+f"(d[1]), "+f"(d[2]), "+f"(d[3])
                 : "r"(a[0]), "r"(a[1]), "r"(a[2]), "r"(a[3]), "r"(b0), "r"(b1));
}

// ---------------- query helpers ----------------
__device__ __forceinline__ bool q_valid(int u, int v) {
    int du = 2 * u - 63, dv = 2 * v - 63;
    return du * du + dv * dv < 1024;
}
__device__ __forceinline__ int slot_to_qidx(const QParam& qp, int slot) {
    if (slot >= qp.nv) return -1;
    int lo = 0, hi = 64;
    while (hi - lo > 1) {
        int mid = (lo + hi) >> 1;
        if (qp.rowstart[mid] <= slot) lo = mid; else hi = mid;
    }
    return lo * 64 + qp.umin[lo] + (slot - qp.rowstart[lo]);
}
__device__ __forceinline__ void qn_of(int qidx, float& x, float& y, float& z) {
    if (qidx < 0) { x = y = z = 0.f; return; }
    int v = qidx >> 6, u = qidx & 63;
    if (!q_valid(u, v)) { x = y = z = 0.f; return; }
    float p =  4.0f * ((u + 0.5f) * (1.0f / 64.0f) - 0.5f);
    float q = -4.0f * ((v + 0.5f) * (1.0f / 64.0f) - 0.5f);
    float r2 = p * p + q * q;
    float inv = 1.0f / (1.0f + r2);
    x = 2.0f * p * inv;
    y = 2.0f * q * inv;
    z = (1.0f - r2) * inv;
}

// -------------------------------------------------------------------------
// Main kernel: grid (7, NSEG, BS), 256 threads, occ 2, single wave.
// Warp layout: 4 q-tiles of 32 queries x 2 ch-groups (ch 0-39 | 40-71).
// B-ldsm halved vs 16q layout; B fragments double-buffered across kk so the
// ldsm latency hides under wgen (FMA2+ex2). A fragments in registers.
// -------------------------------------------------------------------------
__global__ __launch_bounds__(256, 2)
void k_main(const float* __restrict__ fea, const float* __restrict__ nrm,
            const float* __restrict__ msk, const float* __restrict__ lqn,
            QParam qp)
{
    __shared__ __align__(16) float4 pA[2][32];       // {nx0,nx1,ny0,ny1} per pair
    __shared__ __align__(16) float4 pBM[2][32];      // {nz0,nz1, maskf16x2, 0}
    __shared__ __align__(16) char   V_sh[2][VSZ];    // 2 x 72 x 72 fp16

    const int t = threadIdx.x;
    const int wid = t >> 5, lid = t & 31;
    const int qb = blockIdx.x, seg = blockIdx.y, b = blockIdx.z;
    const int slot0 = qb * QT;

    const uint32_t sbV = smem_u32(V_sh);

    const float scale = __expf(lqn[0]) * 0.57735026918962576f;
    const float off   = 1.0f - 4.0f / scale;           // w <= e^4, fp16-safe
    const float k2c   = scale * 1.44269504088896341f;
    const unsigned long long bb2 = pk2(-k2c * off, -k2c * off);

    const float* nb = nrm + (size_t)b * 3 * HW;
    const float* fb = fea + (size_t)b * CIN * HW;
    const float* mb = msk + (size_t)b * HW;

    // warp roles
    const int qt = wid & 3;                            // q-tile (32 queries)
    const int cg = wid >> 2;                           // ch-group: 0 -> 0-39, 1 -> 40-71
    const int lc = lid & 3;                            // col-pair lane index

    // query constants for rows r, r+8, r+16, r+24 (k2c folded in)
    unsigned long long qxx[4], qyy[4], qzz[4];
    #pragma unroll
    for (int qi = 0; qi < 4; qi++) {
        float x, y, z;
        qn_of(slot_to_qidx(qp, slot0 + qt * 32 + (lid >> 2) + 8 * qi), x, y, z);
        qxx[qi] = pk2(x * k2c, x * k2c);
        qyy[qi] = pk2(y * k2c, y * k2c);
        qzz[qi] = pk2(z * k2c, z * k2c);
    }

    // V-load role
    const int vc = t >> 2, vmq = (t & 3) * 16;
    // normals/mask role
    const int nd = t >> 6, nm = t & 63;

    // B ldsm addressing
    const uint32_t bOff4 = (uint32_t)((lid & 15) * PSTR + (lid >> 4) * 16);   // x4
    const uint32_t bOff2 = (uint32_t)((32 + (lid & 7)) * PSTR + ((lid >> 3) & 1) * 16); // x2 rows 32-39

    float acc[2][5][4];
    #pragma unroll
    for (int i = 0; i < 2; i++)
        #pragma unroll
        for (int j = 0; j < 5; j++)
            #pragma unroll
            for (int k = 0; k < 4; k++) acc[i][j][k] = 0.f;

    // static V rows 70 (ones) and 71 (zero), both buffers
    for (int i = t; i < 2 * 2 * 36; i += 256) {
        int buf = i / (2 * 36);
        int rem = i - buf * 2 * 36;
        int r   = rem / 36;
        int wd  = rem - r * 36;
        *(uint32_t*)(V_sh[buf] + (70 + r) * PSTR + wd * 4) =
            (r == 0) ? 0x3C003C00u : 0u;
    }

    const int c0 = (seg * TCH) / NSEG;
    const int c1 = ((seg + 1) * TCH) / NSEG;

    for (int ci = c0; ci < c1; ci++) {
        const int jv = ci & 1;
        const int mb0 = ci * CK;

        // ---- load phase ----
        {
            const float* src = fb + (size_t)vc * HW + mb0 + vmq;
            char* vrow = V_sh[jv] + vc * PSTR + vmq * 2;
            #pragma unroll
            for (int k = 0; k < 4; k++) {
                const float4 v = *(const float4*)(src + k * 4);
                *(uint2*)(vrow + k * 8) =
                    make_uint2(cvt_f16x2(v.x, v.y), cvt_f16x2(v.z, v.w));
                if (vc >= 61) {   // squares -> rows 64..66
                    *(uint2*)(vrow + 3 * PSTR + k * 8) =
                        make_uint2(cvt_f16x2(v.x * v.x, v.y * v.y),
                                   cvt_f16x2(v.z * v.z, v.w * v.w));
                }
            }
            if (t < 192) {
                float v = nb[(size_t)nd * HW + mb0 + nm];
                if (nd == 0)      ((float*)&pA[jv][nm >> 1])[nm & 1] = v;
                else if (nd == 1) ((float*)&pA[jv][nm >> 1])[2 + (nm & 1)] = v;
                else              ((float*)&pBM[jv][nm >> 1])[nm & 1] = v;
                // fp16 normals -> V rows 67..69 (swc reconstruction)
                *(__half*)(V_sh[jv] + (67 + nd) * PSTR + nm * 2) = __float2half(v);
            } else {
                float mk = mb[mb0 + nm];
                *(__half*)((char*)&pBM[jv][nm >> 1] + 8 + (nm & 1) * 2) = __float2half(mk);
            }
        }
        __syncthreads();

        // ---- fused wgen + mma, B double-buffered across kk ----
        {
            const uint32_t vb = sbV + (uint32_t)(jv * VSZ);
            uint32_t bA[2][4], bB[2][4], bC[2][2];

            // prologue: B fragments for kk=0 into buffer 0
            if (cg == 0) {
                ldsm_x4(bA[0][0], bA[0][1], bA[0][2], bA[0][3], vb + bOff4);
                ldsm_x4(bB[0][0], bB[0][1], bB[0][2], bB[0][3], vb + 16 * PSTR + bOff4);
                ldsm_x2(bC[0][0], bC[0][1], vb + bOff2);
            } else {
                ldsm_x4(bA[0][0], bA[0][1], bA[0][2], bA[0][3], vb + 40 * PSTR + bOff4);
                ldsm_x4(bB[0][0], bB[0][1], bB[0][2], bB[0][3], vb + 56 * PSTR + bOff4);
            }

            #pragma unroll
            for (int kk = 0; kk < 4; kk++) {
                const int cur = kk & 1, nxt = cur ^ 1;

                // prefetch B for kk+1 (latency hidden under wgen below)
                if (kk < 3) {
                    const uint32_t ko = (uint32_t)((kk + 1) * 32);
                    if (cg == 0) {
                        ldsm_x4(bA[nxt][0], bA[nxt][1], bA[nxt][2], bA[nxt][3],
                                vb + bOff4 + ko);
                        ldsm_x4(bB[nxt][0], bB[nxt][1], bB[nxt][2], bB[nxt][3],
                                vb + 16 * PSTR + bOff4 + ko);
                        ldsm_x2(bC[nxt][0], bC[nxt][1], vb + bOff2 + ko);
                    } else {
                        ldsm_x4(bA[nxt][0], bA[nxt][1], bA[nxt][2], bA[nxt][3],
                                vb + 40 * PSTR + bOff4 + ko);
                        ldsm_x4(bB[nxt][0], bB[nxt][1], bB[nxt][2], bB[nxt][3],
                                vb + 56 * PSTR + bOff4 + ko);
                    }
                }

                // wgen: A fragments for 2 m16 tiles (32 queries)
                uint32_t aT[2][4];
                #pragma unroll
                for (int h = 0; h < 2; h++) {
                    const int p = 8 * kk + 4 * h + lc;
                    const ulonglong2 uab = *(const ulonglong2*)(&pA[jv][p]);
                    const ulonglong2 ubm = *(const ulonglong2*)(&pBM[jv][p]);
                    const unsigned long long nz2 = ubm.x;
                    const uint32_t mk2 = (uint32_t)ubm.y;
                    #pragma unroll
                    for (int qi = 0; qi < 4; qi++) {
                        unsigned long long c2;
                        FMA2(c2, uab.x, qxx[qi], bb2);
                        FMA2(c2, uab.y, qyy[qi], c2);
                        FMA2(c2, nz2, qzz[qi], c2);
                        float a0, a1;
                        upk2(c2, a0, a1);
                        aT[qi >> 1][2 * h + (qi & 1)] =
                            mul_f16x2(ex2_f16x2(cvt_f16x2(a0, a1)), mk2);
                    }
                }

                // mma with current B buffer
                if (cg == 0) {
                    #pragma unroll
                    for (int ti = 0; ti < 2; ti++) {
                        mma16816(acc[ti][0], aT[ti], bA[cur][0], bA[cur][2]);
                        mma16816(acc[ti][1], aT[ti], bA[cur][1], bA[cur][3]);
                        mma16816(acc[ti][2], aT[ti], bB[cur][0], bB[cur][2]);
                        mma16816(acc[ti][3], aT[ti], bB[cur][1], bB[cur][3]);
                        mma16816(acc[ti][4], aT[ti], bC[cur][0], bC[cur][1]);
                    }
                } else {
                    #pragma unroll
                    for (int ti = 0; ti < 2; ti++) {
                        mma16816(acc[ti][0], aT[ti], bA[cur][0], bA[cur][2]);
                        mma16816(acc[ti][1], aT[ti], bA[cur][1], bA[cur][3]);
                        mma16816(acc[ti][2], aT[ti], bB[cur][0], bB[cur][2]);
                        mma16816(acc[ti][3], aT[ti], bB[cur][1], bB[cur][3]);
                    }
                }
            }
        }
    }

    // ---- write mma partials ----
    {
        const int ntile = cg ? 4 : 5;
        const int chbase = cg * 40 + 2 * lc;
        #pragma unroll
        for (int ti = 0; ti < 2; ti++) {
            const int r0 = slot0 + qt * 32 + ti * 16 + (lid >> 2);
            #pragma unroll
            for (int jj = 0; jj < 5; jj++) {
                if (jj < ntile) {
                    int ch = chbase + 8 * jj;
                    *(float2*)&g_acc[b][seg][r0][ch]     = make_float2(acc[ti][jj][0], acc[ti][jj][1]);
                    *(float2*)&g_acc[b][seg][r0 + 8][ch] = make_float2(acc[ti][jj][2], acc[ti][jj][3]);
                }
            }
        }
    }
}

// -------------------------------------------------------------------------
// Finalize: one 96-thread block per (output pixel, batch).
// ch70 = sumw; swc = qx*ch67 + qy*ch68 + qz*ch69; sq in ch64-66.
// -------------------------------------------------------------------------
__global__ void k_final(float* __restrict__ out, QParam qp)
{
    const int qidx = blockIdx.x;
    const int b    = blockIdx.y;
    const int t    = threadIdx.x;
    const int v = qidx >> 6, u = qidx & 63;

    if (!q_valid(u, v)) {
        if (t < COUT) out[((size_t)b * COUT + t) * NQ + qidx] = 0.f;
        return;
    }
    const int slot = qp.rowstart[v] + (u - qp.umin[v]);

    __shared__ float s[NCH];

    if (t < NCH) {
        float a = 0.f;
        #pragma unroll 7
        for (int i = 0; i < NSEG; i++) a += g_acc[b][i][slot][t];
        s[t] = a;
    }
    __syncthreads();

    const float D = s[70] + 1e-9f;
    float x, y, z;
    qn_of(qidx, x, y, z);

    if (t < 64) {
        out[((size_t)b * COUT + 5 + t) * NQ + qidx] = s[t] / D;
    } else if (t == 64) {
        float swc = x * s[67] + y * s[68] + z * s[69];
        out[((size_t)b * COUT + 0) * NQ + qidx] = swc / D;     // rm_cos
    } else if (t == 65) {
        float var = 0.f;
        #pragma unroll
        for (int i = 0; i < 3; i++) {
            float mean = s[61 + i] / D;
            var += s[64 + i] / D - mean * mean;
        }
        out[((size_t)b * COUT + 1) * NQ + qidx] = var;
    } else if (t >= 66 && t <= 68) {
        float c = (t == 66) ? x : (t == 67) ? y : z;
        out[((size_t)b * COUT + (t - 64)) * NQ + qidx] = c;    // ch 2,3,4
    }
}

// ncu window captures the 4th launch; with (main, final, dummy) per run the
// 4th launch is run-2's k_main.
__global__ void k_dummy() {}

extern "C" void kernel_launch(void* const* d_in, const int* in_sizes, int n_in,
                              void* d_out, int out_size)
{
    const float* fea = (const float*)d_in[0];
    const float* nrm = (const float*)d_in[1];
    const float* msk = (const float*)d_in[2];
    const float* lqn = (const float*)d_in[3];
    float* out = (float*)d_out;

    QParam qp;
    int n = 0;
    for (int v = 0; v < 64; v++) {
        qp.rowstart[v] = n;
        int first = -1;
        for (int u = 0; u < 64; u++) {
            int du = 2 * u - 63, dv = 2 * v - 63;
            if (du * du + dv * dv < 1024) {
                if (first < 0) first = u;
                n++;
            }
        }
        qp.umin[v] = (first < 0) ? 0 : first;
    }
    qp.rowstart[64] = n;
    qp.nv = n;

    const int qblocks = (n + QT - 1) / QT;   // 7

    dim3 g1(qblocks, NSEG, BS);
    k_main<<<g1, 256>>>(fea, nrm, msk, lqn, qp);
    k_final<<<dim3(NQ, BS), 96>>>(out, qp);
    k_dummy<<<1, 32>>>();
}

// round 13
// speedup vs baseline: 1.2400x; 1.2400x over previous
#include <cuda_runtime.h>
#include <cuda_fp16.h>
#include <math.h>
#include <stdint.h>

// Problem constants
#define HW     36864          // 192*192
#define CIN    64
#define BS     2
#define NQ     4096
#define COUT   69

// Tiling
#define QT     128            // queries per block
#define CK     128            // m per chunk
#define NSEG   31             // grid 7*31*2 = 434 <= 148*occ3 = 444 (single wave)
#define TCH    (HW / CK)      // 288 chunks
#define MAXV   896            // 7 * 128 slots
#define PSTR   272            // V row stride bytes (128 fp16 + 16B pad, conflict-free)
#define NCH    72             // V rows: 64 fea + 3 sq + 3 nrm + ones + zero
#define VROWS  72
#define VBLOB  (VROWS * PSTR) // 19584 B per chunk
#define NBLOB  1792           // pA float4[64] | pB float2[64] | pM u32[64]
#define NTILE  9              // n8 mma tiles (ch 0..71)

// dynamic smem layout: 3 V buffers then 3 N buffers
#define SM_V(j)  ((j) * VBLOB)
#define SM_N(j)  (3 * VBLOB + (j) * NBLOB)
#define SMEM_TOT (3 * VBLOB + 3 * NBLOB)   // 64128 B

struct QParam {
    int nv;
    int rowstart[65];
    int umin[64];
};

// Precomputed chunk images + split-K partials
__device__ __align__(16) char  g_V[BS][TCH][VBLOB];
__device__ __align__(16) char  g_N[BS][TCH][NBLOB];
__device__ __align__(16) float g_acc[BS][NSEG][MAXV][NCH];

// ---------------- PTX helpers ----------------
#define FMA2(d, a, b, c) asm("fma.rn.f32x2 %0, %1, %2, %3;" : "=l"(d) : "l"(a), "l"(b), "l"(c))

__device__ __forceinline__ uint32_t smem_u32(const void* p) {
    uint32_t a;
    asm("{ .reg .u64 t; cvta.to.shared.u64 t, %1; cvt.u32.u64 %0, t; }"
        : "=r"(a) : "l"(p));
    return a;
}
__device__ __forceinline__ unsigned long long pk2(float lo, float hi) {
    unsigned long long r;
    asm("mov.b64 %0, {%1, %2};" : "=l"(r) : "f"(lo), "f"(hi));
    return r;
}
__device__ __forceinline__ void upk2(unsigned long long v, float& lo, float& hi) {
    asm("mov.b64 {%0, %1}, %2;" : "=f"(lo), "=f"(hi) : "l"(v));
}
__device__ __forceinline__ uint32_t cvt_f16x2(float lo, float hi) {
    uint32_t r; asm("cvt.rn.f16x2.f32 %0, %1, %2;" : "=r"(r) : "f"(hi), "f"(lo)); return r;
}
__device__ __forceinline__ uint32_t ex2_f16x2(uint32_t a) {
    uint32_t r; asm("ex2.approx.f16x2 %0, %1;" : "=r"(r) : "r"(a)); return r;
}
__device__ __forceinline__ uint32_t mul_f16x2(uint32_t a, uint32_t b) {
    uint32_t r; asm("mul.rn.f16x2 %0, %1, %2;" : "=r"(r) : "r"(a), "r"(b)); return r;
}
__device__ __forceinline__ void cpa16(uint32_t dst, const void* src) {
    asm volatile("cp.async.cg.shared.global [%0], [%1], 16;" :: "r"(dst), "l"(src));
}
#define CP_COMMIT() asm volatile("cp.async.commit_group;" ::: "memory")
#define CP_WAIT1()  asm volatile("cp.async.wait_group 1;" ::: "memory")
#define CP_WAIT0()  asm volatile("cp.async.wait_group 0;" ::: "memory")

__device__ __forceinline__ void ldsm_x4(uint32_t& r0, uint32_t& r1, uint32_t& r2,
                                        uint32_t& r3, uint32_t addr) {
    asm volatile("ldmatrix.sync.aligned.m8n8.x4.shared.b16 {%0,%1,%2,%3}, [%4];"
                 : "=r"(r0), "=r"(r1), "=r"(r2), "=r"(r3) : "r"(addr));
}
__device__ __forceinline__ void ldsm_x2(uint32_t& r0, uint32_t& r1, uint32_t addr) {
    asm volatile("ldmatrix.sync.aligned.m8n8.x2.shared.b16 {%0,%1}, [%2];"
                 : "=r"(r0), "=r"(r1) : "r"(addr));
}
__device__ __forceinline__ void mma16816(float* d, const uint32_t* a,
                                         uint32_t b0, uint32_t b1) {
    asm volatile("mma.sync.aligned.m16n8k16.row.col.f32.f16.f16.f32 "
                 "{%0,%1,%2,%3}, {%4,%5,%6,%7}, {%8,%9}, {%0,%1,%2,%3};"
                 : "+f"(d[0]), "+f"(d[1]), "+f"(d[2]), "+f"(d[3])
                 : "r"(a[0]), "r"(a[1]), "r"(a[2]), "r"(a[3]), "r"(b0), "r"(b1));
}

// ---------------- query helpers ----------------
__device__ __forceinline__ bool q_valid(int u, int v) {
    int du = 2 * u - 63, dv = 2 * v - 63;
    return du * du + dv * dv < 1024;
}
__device__ __forceinline__ int slot_to_qidx(const QParam& qp, int slot) {
    if (slot >= qp.nv) return -1;
    int lo = 0, hi = 64;
    while (hi - lo > 1) {
        int mid = (lo + hi) >> 1;
        if (qp.rowstart[mid] <= slot) lo = mid; else hi = mid;
    }
    return lo * 64 + qp.umin[lo] + (slot - qp.rowstart[lo]);
}
__device__ __forceinline__ void qn_of(int qidx, float& x, float& y, float& z) {
    if (qidx < 0) { x = y = z = 0.f; return; }
    int v = qidx >> 6, u = qidx & 63;
    if (!q_valid(u, v)) { x = y = z = 0.f; return; }
    float p =  4.0f * ((u + 0.5f) * (1.0f / 64.0f) - 0.5f);
    float q = -4.0f * ((v + 0.5f) * (1.0f / 64.0f) - 0.5f);
    float r2 = p * p + q * q;
    float inv = 1.0f / (1.0f + r2);
    x = 2.0f * p * inv;
    y = 2.0f * q * inv;
    z = (1.0f - r2) * inv;
}

// -------------------------------------------------------------------------
// k_prep: build per-chunk fp16 V-tile images + packed normal/mask blobs ONCE
// (previously each of the 7 q-block CTAs redid this conversion per chunk).
// Grid (TCH, BS), 256 threads.
// -------------------------------------------------------------------------
__global__ __launch_bounds__(256)
void k_prep(const float* __restrict__ fea, const float* __restrict__ nrm,
            const float* __restrict__ msk)
{
    const int ch = blockIdx.x, b = blockIdx.y;
    const int t = threadIdx.x;
    const int mb0 = ch * CK;
    char* vdst = &g_V[b][ch][0];
    char* ndst = &g_N[b][ch][0];

    // fea rows 0-63 (+ squares of 61-63 into rows 64-66)
    {
        const int vc = t >> 2, vq = (t & 3) * 32;
        const float* src = fea + ((size_t)b * CIN + vc) * HW + mb0 + vq;
        uint32_t h[16], s[16];
        #pragma unroll
        for (int k = 0; k < 8; k++) {
            const float4 v = *(const float4*)(src + k * 4);
            h[2 * k]     = cvt_f16x2(v.x, v.y);
            h[2 * k + 1] = cvt_f16x2(v.z, v.w);
            if (vc >= 61) {
                s[2 * k]     = cvt_f16x2(v.x * v.x, v.y * v.y);
                s[2 * k + 1] = cvt_f16x2(v.z * v.z, v.w * v.w);
            }
        }
        uint4* d0 = (uint4*)(vdst + vc * PSTR + vq * 2);
        #pragma unroll
        for (int k = 0; k < 4; k++)
            d0[k] = make_uint4(h[4 * k], h[4 * k + 1], h[4 * k + 2], h[4 * k + 3]);
        if (vc >= 61) {
            uint4* d1 = (uint4*)(vdst + (vc + 3) * PSTR + vq * 2);
            #pragma unroll
            for (int k = 0; k < 4; k++)
                d1[k] = make_uint4(s[4 * k], s[4 * k + 1], s[4 * k + 2], s[4 * k + 3]);
        }
    }
    // normals: fp16 rows 67-69 + fp32 packed pA/pB
    for (int idx = t; idx < 3 * CK; idx += 256) {
        int d = idx >> 7, m = idx & 127;
        float v = nrm[((size_t)b * 3 + d) * HW + mb0 + m];
        *(__half*)(vdst + (67 + d) * PSTR + m * 2) = __float2half(v);
        int pp = m >> 1;
        if (d < 2) *(float*)(ndst + pp * 16 + d * 8 + (m & 1) * 4) = v;
        else       *(float*)(ndst + 1024 + pp * 8 + (m & 1) * 4) = v;
    }
    // mask -> f16x2 pairs
    for (int idx = t; idx < CK; idx += 256) {
        float mk = msk[(size_t)b * HW + mb0 + idx];
        *(__half*)(ndst + 1536 + (idx >> 1) * 4 + (idx & 1) * 2) = __float2half(mk);
    }
    // rows 70 (ones) / 71 (zero)
    for (int i = t; i < 2 * 68; i += 256) {
        int r = i / 68, w = i - r * 68;
        *(uint32_t*)(vdst + (70 + r) * PSTR + w * 4) = (r == 0) ? 0x3C003C00u : 0u;
    }
}

// -------------------------------------------------------------------------
// k_main: grid (7, NSEG, BS), 256 threads, occ 3, single wave.
// Per 128-m chunk: cp.async the prebuilt V+N images (triple-buffered, one
// __syncthreads), then fused wgen + mma (16 queries/warp x 72 ch, kk 0..7).
// -------------------------------------------------------------------------
__global__ __launch_bounds__(256, 3)
void k_main(const float* __restrict__ lqn, QParam qp)
{
    extern __shared__ char smem[];
    const uint32_t sb = smem_u32(smem);

    const int t = threadIdx.x;
    const int wid = t >> 5, lid = t & 31;
    const int qb = blockIdx.x, seg = blockIdx.y, b = blockIdx.z;
    const int slot0 = qb * QT;

    const float scale = __expf(lqn[0]) * 0.57735026918962576f;
    const float off   = 1.0f - 4.0f / scale;           // w <= e^4, fp16-safe
    const float k2c   = scale * 1.44269504088896341f;
    const unsigned long long bb2 = pk2(-k2c * off, -k2c * off);

    // fused-A role: warp owns queries [wid*16, wid*16+16); lane rows l>>2, +8
    float qx0, qy0, qz0, qx1, qy1, qz1;
    qn_of(slot_to_qidx(qp, slot0 + wid * 16 + (lid >> 2)),     qx0, qy0, qz0);
    qn_of(slot_to_qidx(qp, slot0 + wid * 16 + (lid >> 2) + 8), qx1, qy1, qz1);
    const unsigned long long qxx[2] = { pk2(qx0 * k2c, qx0 * k2c), pk2(qx1 * k2c, qx1 * k2c) };
    const unsigned long long qyy[2] = { pk2(qy0 * k2c, qy0 * k2c), pk2(qy1 * k2c, qy1 * k2c) };
    const unsigned long long qzz[2] = { pk2(qz0 * k2c, qz0 * k2c), pk2(qz1 * k2c, qz1 * k2c) };
    const int lc = lid & 3;

    const uint32_t bOff4 = (uint32_t)((lid & 15) * PSTR + (lid >> 4) * 16);
    const uint32_t bOff2 = (uint32_t)((64 + (lid & 7)) * PSTR + ((lid >> 3) & 1) * 16);

    float acc[NTILE][4];
    #pragma unroll
    for (int j = 0; j < NTILE; j++)
        #pragma unroll
        for (int k = 0; k < 4; k++) acc[j][k] = 0.f;

    const int c0 = (seg * TCH) / NSEG;
    const int c1 = ((seg + 1) * TCH) / NSEG;

    // prologue copy for c0 into buffer 0
    {
        const char* gv = &g_V[b][c0][0];
        for (int i = t * 16; i < VBLOB; i += 256 * 16) cpa16(sb + SM_V(0) + i, gv + i);
        if (t < NBLOB / 16) cpa16(sb + SM_N(0) + t * 16, &g_N[b][c0][0] + t * 16);
        CP_COMMIT();
    }

    for (int ci = c0; ci < c1; ci++) {
        const int li = ci - c0;
        const int jv = li % 3;

        if (ci + 1 < c1) {   // stream chunk ci+1 into the third buffer
            const int jn = (li + 1) % 3;
            const char* gv = &g_V[b][ci + 1][0];
            for (int i = t * 16; i < VBLOB; i += 256 * 16) cpa16(sb + SM_V(jn) + i, gv + i);
            if (t < NBLOB / 16) cpa16(sb + SM_N(jn) + t * 16, &g_N[b][ci + 1][0] + t * 16);
            CP_COMMIT();
            CP_WAIT1();      // ci's data complete; ci+1 still in flight
        } else {
            CP_WAIT0();
        }
        __syncthreads();

        // ---- fused wgen + mma over 8 k-subtiles of 16 m ----
        const uint32_t vb = sb + (uint32_t)SM_V(jv);
        const char* np = smem + SM_N(jv);
        #pragma unroll
        for (int kk = 0; kk < 8; kk++) {
            uint32_t bf[4][4], bC[2];
            #pragma unroll
            for (int g = 0; g < 4; g++)
                ldsm_x4(bf[g][0], bf[g][1], bf[g][2], bf[g][3],
                        vb + bOff4 + g * 16 * PSTR + kk * 32);
            ldsm_x2(bC[0], bC[1], vb + bOff2 + kk * 32);

            uint32_t a[4];
            #pragma unroll
            for (int h = 0; h < 2; h++) {
                const int pp = 8 * kk + 4 * h + lc;
                const ulonglong2 uab = *(const ulonglong2*)(np + pp * 16);
                const unsigned long long nz2 = *(const unsigned long long*)(np + 1024 + pp * 8);
                const uint32_t mk2 = *(const uint32_t*)(np + 1536 + pp * 4);
                #pragma unroll
                for (int qi = 0; qi < 2; qi++) {
                    unsigned long long c2;
                    FMA2(c2, uab.x, qxx[qi], bb2);
                    FMA2(c2, uab.y, qyy[qi], c2);
                    FMA2(c2, nz2, qzz[qi], c2);
                    float a0, a1;
                    upk2(c2, a0, a1);
                    a[2 * h + qi] = mul_f16x2(ex2_f16x2(cvt_f16x2(a0, a1)), mk2);
                }
            }

            #pragma unroll
            for (int jj = 0; jj < 8; jj++)
                mma16816(acc[jj], a, bf[jj >> 1][jj & 1], bf[jj >> 1][(jj & 1) + 2]);
            mma16816(acc[8], a, bC[0], bC[1]);
        }
        __syncthreads();   // all warps done with buf jv before it is refilled
    }

    // ---- write mma partials ----
    {
        const int r0 = slot0 + wid * 16 + (lid >> 2);
        const int chb = 2 * lc;
        #pragma unroll
        for (int jj = 0; jj < NTILE; jj++) {
            int ch = 8 * jj + chb;
            *(float2*)&g_acc[b][seg][r0][ch]     = make_float2(acc[jj][0], acc[jj][1]);
            *(float2*)&g_acc[b][seg][r0 + 8][ch] = make_float2(acc[jj][2], acc[jj][3]);
        }
    }
}

// -------------------------------------------------------------------------
// Finalize: one 96-thread block per (output pixel, batch).
// ch70 = sumw; swc = qx*ch67 + qy*ch68 + qz*ch69; sq in ch64-66.
// -------------------------------------------------------------------------
__global__ void k_final(float* __restrict__ out, QParam qp)
{
    const int qidx = blockIdx.x;
    const int b    = blockIdx.y;
    const int t    = threadIdx.x;
    const int v = qidx >> 6, u = qidx & 63;

    if (!q_valid(u, v)) {
        if (t < COUT) out[((size_t)b * COUT + t) * NQ + qidx] = 0.f;
        return;
    }
    const int slot = qp.rowstart[v] + (u - qp.umin[v]);

    __shared__ float s[NCH];

    if (t < NCH) {
        float a = 0.f;
        #pragma unroll 8
        for (int i = 0; i < NSEG; i++) a += g_acc[b][i][slot][t];
        s[t] = a;
    }
    __syncthreads();

    const float D = s[70] + 1e-9f;
    float x, y, z;
    qn_of(qidx, x, y, z);

    if (t < 64) {
        out[((size_t)b * COUT + 5 + t) * NQ + qidx] = s[t] / D;
    } else if (t == 64) {
        float swc = x * s[67] + y * s[68] + z * s[69];
        out[((size_t)b * COUT + 0) * NQ + qidx] = swc / D;     // rm_cos
    } else if (t == 65) {
        float var = 0.f;
        #pragma unroll
        for (int i = 0; i < 3; i++) {
            float mean = s[61 + i] / D;
            var += s[64 + i] / D - mean * mean;
        }
        out[((size_t)b * COUT + 1) * NQ + qidx] = var;
    } else if (t >= 66 && t <= 68) {
        float c = (t == 66) ? x : (t == 67) ? y : z;
        out[((size_t)b * COUT + (t - 64)) * NQ + qidx] = c;    // ch 2,3,4
    }
}

extern "C" void kernel_launch(void* const* d_in, const int* in_sizes, int n_in,
                              void* d_out, int out_size)
{
    const float* fea = (const float*)d_in[0];
    const float* nrm = (const float*)d_in[1];
    const float* msk = (const float*)d_in[2];
    const float* lqn = (const float*)d_in[3];
    float* out = (float*)d_out;

    QParam qp;
    int n = 0;
    for (int v = 0; v < 64; v++) {
        qp.rowstart[v] = n;
        int first = -1;
        for (int u = 0; u < 64; u++) {
            int du = 2 * u - 63, dv = 2 * v - 63;
            if (du * du + dv * dv < 1024) {
                if (first < 0) first = u;
                n++;
            }
        }
        qp.umin[v] = (first < 0) ? 0 : first;
    }
    qp.rowstart[64] = n;
    qp.nv = n;

    const int qblocks = (n + QT - 1) / QT;   // 7

    static int smem_set = 0;
    if (!smem_set) {
        cudaFuncSetAttribute(k_main, cudaFuncAttributeMaxDynamicSharedMemorySize,
                             SMEM_TOT);
        smem_set = 1;
    }

    k_prep<<<dim3(TCH, BS), 256>>>(fea, nrm, msk);
    k_main<<<dim3(qblocks, NSEG, BS), 256, SMEM_TOT>>>(lqn, qp);
    k_final<<<dim3(NQ, BS), 96>>>(out, qp);
}

// round 14
// speedup vs baseline: 1.2839x; 1.0354x over previous
#include <cuda_runtime.h>
#include <cuda_fp16.h>
#include <math.h>
#include <stdint.h>

// Problem constants
#define HW     36864          // 192*192
#define CIN    64
#define BS     2
#define NQ     4096
#define COUT   69

// Tiling
#define QT     128            // queries per block
#define CK     128            // m per chunk
#define NSEG   31             // grid 7*31*2 = 434 <= 148*occ3 = 444 (single wave)
#define TCH    (HW / CK)      // 288 chunks
#define MAXV   896            // 7 * 128 slots
#define PSTR   272            // V row stride bytes (128 fp16 + 16B pad)
#define NCH    72             // V rows: 64 fea + 3 sq + 3 nrm + ones + zero
#define VROWS  72
#define VBLOB  (VROWS * PSTR) // 19584 B per chunk
#define NBLOB  1792           // pA float4[64] | pB float2[64] | pM u32[64]
#define NTILE  9              // n8 mma tiles (ch 0..71)

// dynamic smem layout: 3 V buffers then 3 N buffers
#define SM_V(j)  ((j) * VBLOB)
#define SM_N(j)  (3 * VBLOB + (j) * NBLOB)
#define SMEM_TOT (3 * VBLOB + 3 * NBLOB)   // 64128 B

struct QParam {
    int nv;
    int rowstart[65];
    int umin[64];
};

// Precomputed chunk images + split-K partials
__device__ __align__(16) char  g_V[BS][TCH][VBLOB];
__device__ __align__(16) char  g_N[BS][TCH][NBLOB];
__device__ __align__(16) float g_acc[BS][NSEG][MAXV][NCH];

// ---------------- PTX helpers ----------------
#define FMA2(d, a, b, c) asm("fma.rn.f32x2 %0, %1, %2, %3;" : "=l"(d) : "l"(a), "l"(b), "l"(c))

__device__ __forceinline__ uint32_t smem_u32(const void* p) {
    uint32_t a;
    asm("{ .reg .u64 t; cvta.to.shared.u64 t, %1; cvt.u32.u64 %0, t; }"
        : "=r"(a) : "l"(p));
    return a;
}
__device__ __forceinline__ unsigned long long pk2(float lo, float hi) {
    unsigned long long r;
    asm("mov.b64 %0, {%1, %2};" : "=l"(r) : "f"(lo), "f"(hi));
    return r;
}
__device__ __forceinline__ void upk2(unsigned long long v, float& lo, float& hi) {
    asm("mov.b64 {%0, %1}, %2;" : "=f"(lo), "=f"(hi) : "l"(v));
}
__device__ __forceinline__ uint32_t cvt_f16x2(float lo, float hi) {
    uint32_t r; asm("cvt.rn.f16x2.f32 %0, %1, %2;" : "=r"(r) : "f"(hi), "f"(lo)); return r;
}
__device__ __forceinline__ uint32_t ex2_f16x2(uint32_t a) {
    uint32_t r; asm("ex2.approx.f16x2 %0, %1;" : "=r"(r) : "r"(a)); return r;
}
__device__ __forceinline__ uint32_t mul_f16x2(uint32_t a, uint32_t b) {
    uint32_t r; asm("mul.rn.f16x2 %0, %1, %2;" : "=r"(r) : "r"(a), "r"(b)); return r;
}
__device__ __forceinline__ void cpa16(uint32_t dst, const void* src) {
    asm volatile("cp.async.cg.shared.global [%0], [%1], 16;" :: "r"(dst), "l"(src));
}
#define CP_COMMIT() asm volatile("cp.async.commit_group;" ::: "memory")
#define CP_WAIT1()  asm volatile("cp.async.wait_group 1;" ::: "memory")
#define CP_WAIT0()  asm volatile("cp.async.wait_group 0;" ::: "memory")

__device__ __forceinline__ void ldsm_x4(uint32_t& r0, uint32_t& r1, uint32_t& r2,
                                        uint32_t& r3, uint32_t addr) {
    asm volatile("ldmatrix.sync.aligned.m8n8.x4.shared.b16 {%0,%1,%2,%3}, [%4];"
                 : "=r"(r0), "=r"(r1), "=r"(r2), "=r"(r3) : "r"(addr));
}
__device__ __forceinline__ void ldsm_x2(uint32_t& r0, uint32_t& r1, uint32_t addr) {
    asm volatile("ldmatrix.sync.aligned.m8n8.x2.shared.b16 {%0,%1}, [%2];"
                 : "=r"(r0), "=r"(r1) : "r"(addr));
}
__device__ __forceinline__ void mma16816(float* d, const uint32_t* a,
                                         uint32_t b0, uint32_t b1) {
    asm volatile("mma.sync.aligned.m16n8k16.row.col.f32.f16.f16.f32 "
                 "{%0,%1,%2,%3}, {%4,%5,%6,%7}, {%8,%9}, {%0,%1,%2,%3};"
                 : "+f"(d[0]), "+f"(d[1]), "+f"(d[2]), "+f"(d[3])
                 : "r"(a[0]), "r"(a[1]), "r"(a[2]), "r"(a[3]), "r"(b0), "r"(b1));
}

// ---------------- query helpers ----------------
__device__ __forceinline__ bool q_valid(int u, int v) {
    int du = 2 * u - 63, dv = 2 * v - 63;
    return du * du + dv * dv < 1024;
}
__device__ __forceinline__ int slot_to_qidx(const QParam& qp, int slot) {
    if (slot >= qp.nv) return -1;
    int lo = 0, hi = 64;
    while (hi - lo > 1) {
        int mid = (lo + hi) >> 1;
        if (qp.rowstart[mid] <= slot) lo = mid; else hi = mid;
    }
    return lo * 64 + qp.umin[lo] + (slot - qp.rowstart[lo]);
}
__device__ __forceinline__ void qn_of(int qidx, float& x, float& y, float& z) {
    if (qidx < 0) { x = y = z = 0.f; return; }
    int v = qidx >> 6, u = qidx & 63;
    if (!q_valid(u, v)) { x = y = z = 0.f; return; }
    float p =  4.0f * ((u + 0.5f) * (1.0f / 64.0f) - 0.5f);
    float q = -4.0f * ((v + 0.5f) * (1.0f / 64.0f) - 0.5f);
    float r2 = p * p + q * q;
    float inv = 1.0f / (1.0f + r2);
    x = 2.0f * p * inv;
    y = 2.0f * q * inv;
    z = (1.0f - r2) * inv;
}

// -------------------------------------------------------------------------
// k_prep: build per-chunk fp16 V-tile images + packed normal/mask blobs.
// Grid (TCH, 2, BS): two CTAs per chunk (half = 32 fea rows + half extras)
// for 2x latency-hiding parallelism.
// -------------------------------------------------------------------------
__global__ __launch_bounds__(256)
void k_prep(const float* __restrict__ fea, const float* __restrict__ nrm,
            const float* __restrict__ msk)
{
    const int ch = blockIdx.x, half = blockIdx.y, b = blockIdx.z;
    const int t = threadIdx.x;
    const int mb0 = ch * CK;
    char* vdst = &g_V[b][ch][0];
    char* ndst = &g_N[b][ch][0];

    // fea rows [half*32, half*32+32) (+ squares of 61-63 into rows 64-66)
    {
        const int vc = half * 32 + (t >> 3);       // 8 threads per row
        const int vq = (t & 7) * 16;               // 16 floats per thread
        const float* src = fea + ((size_t)b * CIN + vc) * HW + mb0 + vq;
        uint32_t h[8], s[8];
        #pragma unroll
        for (int k = 0; k < 4; k++) {
            const float4 v = *(const float4*)(src + k * 4);
            h[2 * k]     = cvt_f16x2(v.x, v.y);
            h[2 * k + 1] = cvt_f16x2(v.z, v.w);
            if (vc >= 61) {
                s[2 * k]     = cvt_f16x2(v.x * v.x, v.y * v.y);
                s[2 * k + 1] = cvt_f16x2(v.z * v.z, v.w * v.w);
            }
        }
        uint4* d0 = (uint4*)(vdst + vc * PSTR + vq * 2);
        d0[0] = make_uint4(h[0], h[1], h[2], h[3]);
        d0[1] = make_uint4(h[4], h[5], h[6], h[7]);
        if (vc >= 61) {
            uint4* d1 = (uint4*)(vdst + (vc + 3) * PSTR + vq * 2);
            d1[0] = make_uint4(s[0], s[1], s[2], s[3]);
            d1[1] = make_uint4(s[4], s[5], s[6], s[7]);
        }
    }
    if (half == 0) {
        // normals: fp16 rows 67-69 + fp32 packed pA/pB
        for (int idx = t; idx < 3 * CK; idx += 256) {
            int d = idx >> 7, m = idx & 127;
            float v = nrm[((size_t)b * 3 + d) * HW + mb0 + m];
            *(__half*)(vdst + (67 + d) * PSTR + m * 2) = __float2half(v);
            int pp = m >> 1;
            if (d < 2) *(float*)(ndst + pp * 16 + d * 8 + (m & 1) * 4) = v;
            else       *(float*)(ndst + 1024 + pp * 8 + (m & 1) * 4) = v;
        }
    } else {
        // mask -> f16x2 pairs
        if (t < CK) {
            float mk = msk[(size_t)b * HW + mb0 + t];
            *(__half*)(ndst + 1536 + (t >> 1) * 4 + (t & 1) * 2) = __float2half(mk);
        }
        // rows 70 (ones) / 71 (zero)
        for (int i = t; i < 2 * 68; i += 256) {
            int r = i / 68, w = i - r * 68;
            *(uint32_t*)(vdst + (70 + r) * PSTR + w * 4) = (r == 0) ? 0x3C003C00u : 0u;
        }
    }
}

// -------------------------------------------------------------------------
// k_main: grid (7, NSEG, BS), 256 threads, occ 3, single wave.
// Per 128-m chunk: cp.async the prebuilt V+N images (triple-buffered, ONE
// __syncthreads), then fused wgen + mma (16 queries/warp x 72 ch, kk 0..7).
// Trailing sync removed: with 3 buffers, the buffer written at iter li+1
// ((li+1)%3) never collides with a straggler still reading (li-1)%3.
// -------------------------------------------------------------------------
__global__ __launch_bounds__(256, 3)
void k_main(const float* __restrict__ lqn, QParam qp)
{
    extern __shared__ char smem[];
    const uint32_t sb = smem_u32(smem);

    const int t = threadIdx.x;
    const int wid = t >> 5, lid = t & 31;
    const int qb = blockIdx.x, seg = blockIdx.y, b = blockIdx.z;
    const int slot0 = qb * QT;

    const float scale = __expf(lqn[0]) * 0.57735026918962576f;
    const float off   = 1.0f - 4.0f / scale;           // w <= e^4, fp16-safe
    const float k2c   = scale * 1.44269504088896341f;
    const unsigned long long bb2 = pk2(-k2c * off, -k2c * off);

    // fused-A role: warp owns queries [wid*16, wid*16+16); lane rows l>>2, +8
    float qx0, qy0, qz0, qx1, qy1, qz1;
    qn_of(slot_to_qidx(qp, slot0 + wid * 16 + (lid >> 2)),     qx0, qy0, qz0);
    qn_of(slot_to_qidx(qp, slot0 + wid * 16 + (lid >> 2) + 8), qx1, qy1, qz1);
    const unsigned long long qxx[2] = { pk2(qx0 * k2c, qx0 * k2c), pk2(qx1 * k2c, qx1 * k2c) };
    const unsigned long long qyy[2] = { pk2(qy0 * k2c, qy0 * k2c), pk2(qy1 * k2c, qy1 * k2c) };
    const unsigned long long qzz[2] = { pk2(qz0 * k2c, qz0 * k2c), pk2(qz1 * k2c, qz1 * k2c) };
    const int lc = lid & 3;

    const uint32_t bOff4 = (uint32_t)((lid & 15) * PSTR + (lid >> 4) * 16);
    const uint32_t bOff2 = (uint32_t)((64 + (lid & 7)) * PSTR + ((lid >> 3) & 1) * 16);

    float acc[NTILE][4];
    #pragma unroll
    for (int j = 0; j < NTILE; j++)
        #pragma unroll
        for (int k = 0; k < 4; k++) acc[j][k] = 0.f;

    const int c0 = (seg * TCH) / NSEG;
    const int c1 = ((seg + 1) * TCH) / NSEG;

    // prologue copy for c0 into buffer 0
    {
        const char* gv = &g_V[b][c0][0];
        for (int i = t * 16; i < VBLOB; i += 256 * 16) cpa16(sb + SM_V(0) + i, gv + i);
        if (t < NBLOB / 16) cpa16(sb + SM_N(0) + t * 16, &g_N[b][c0][0] + t * 16);
        CP_COMMIT();
    }

    for (int ci = c0; ci < c1; ci++) {
        const int li = ci - c0;
        const int jv = li % 3;

        if (ci + 1 < c1) {   // stream chunk ci+1 into the third buffer
            const int jn = (li + 1) % 3;
            const char* gv = &g_V[b][ci + 1][0];
            for (int i = t * 16; i < VBLOB; i += 256 * 16) cpa16(sb + SM_V(jn) + i, gv + i);
            if (t < NBLOB / 16) cpa16(sb + SM_N(jn) + t * 16, &g_N[b][ci + 1][0] + t * 16);
            CP_COMMIT();
            CP_WAIT1();      // ci's data complete; ci+1 still in flight
        } else {
            CP_WAIT0();
        }
        __syncthreads();

        // ---- fused wgen + mma over 8 k-subtiles of 16 m ----
        const uint32_t vb = sb + (uint32_t)SM_V(jv);
        const char* np = smem + SM_N(jv);
        #pragma unroll
        for (int kk = 0; kk < 8; kk++) {
            uint32_t bf[4][4], bC[2];
            #pragma unroll
            for (int g = 0; g < 4; g++)
                ldsm_x4(bf[g][0], bf[g][1], bf[g][2], bf[g][3],
                        vb + bOff4 + g * 16 * PSTR + kk * 32);
            ldsm_x2(bC[0], bC[1], vb + bOff2 + kk * 32);

            uint32_t a[4];
            #pragma unroll
            for (int h = 0; h < 2; h++) {
                const int pp = 8 * kk + 4 * h + lc;
                const ulonglong2 uab = *(const ulonglong2*)(np + pp * 16);
                const unsigned long long nz2 = *(const unsigned long long*)(np + 1024 + pp * 8);
                const uint32_t mk2 = *(const uint32_t*)(np + 1536 + pp * 4);
                #pragma unroll
                for (int qi = 0; qi < 2; qi++) {
                    unsigned long long c2;
                    FMA2(c2, uab.x, qxx[qi], bb2);
                    FMA2(c2, uab.y, qyy[qi], c2);
                    FMA2(c2, nz2, qzz[qi], c2);
                    float a0, a1;
                    upk2(c2, a0, a1);
                    a[2 * h + qi] = mul_f16x2(ex2_f16x2(cvt_f16x2(a0, a1)), mk2);
                }
            }

            #pragma unroll
            for (int jj = 0; jj < 8; jj++)
                mma16816(acc[jj], a, bf[jj >> 1][jj & 1], bf[jj >> 1][(jj & 1) + 2]);
            mma16816(acc[8], a, bC[0], bC[1]);
        }
        // no trailing sync: triple-buffer parity keeps writer/reader disjoint
    }

    // ---- write mma partials ----
    {
        const int r0 = slot0 + wid * 16 + (lid >> 2);
        const int chb = 2 * lc;
        #pragma unroll
        for (int jj = 0; jj < NTILE; jj++) {
            int ch = 8 * jj + chb;
            *(float2*)&g_acc[b][seg][r0][ch]     = make_float2(acc[jj][0], acc[jj][1]);
            *(float2*)&g_acc[b][seg][r0 + 8][ch] = make_float2(acc[jj][2], acc[jj][3]);
        }
    }
}

// -------------------------------------------------------------------------
// Finalize: one 96-thread block per (output pixel, batch). Segment loops
// FULLY unrolled -> 31 independent LDGs in flight per thread.
// -------------------------------------------------------------------------
__global__ void k_final(float* __restrict__ out, QParam qp)
{
    const int qidx = blockIdx.x;
    const int b    = blockIdx.y;
    const int t    = threadIdx.x;
    const int v = qidx >> 6, u = qidx & 63;

    if (!q_valid(u, v)) {
        if (t < COUT) out[((size_t)b * COUT + t) * NQ + qidx] = 0.f;
        return;
    }
    const int slot = qp.rowstart[v] + (u - qp.umin[v]);

    __shared__ float s[NCH];

    if (t < NCH) {
        float a = 0.f;
        #pragma unroll
        for (int i = 0; i < NSEG; i++) a += g_acc[b][i][slot][t];
        s[t] = a;
    }
    __syncthreads();

    const float D = s[70] + 1e-9f;
    float x, y, z;
    qn_of(qidx, x, y, z);

    if (t < 64) {
        out[((size_t)b * COUT + 5 + t) * NQ + qidx] = s[t] / D;
    } else if (t == 64) {
        float swc = x * s[67] + y * s[68] + z * s[69];
        out[((size_t)b * COUT + 0) * NQ + qidx] = swc / D;     // rm_cos
    } else if (t == 65) {
        float var = 0.f;
        #pragma unroll
        for (int i = 0; i < 3; i++) {
            float mean = s[61 + i] / D;
            var += s[64 + i] / D - mean * mean;
        }
        out[((size_t)b * COUT + 1) * NQ + qidx] = var;
    } else if (t >= 66 && t <= 68) {
        float c = (t == 66) ? x : (t == 67) ? y : z;
        out[((size_t)b * COUT + (t - 64)) * NQ + qidx] = c;    // ch 2,3,4
    }
}

extern "C" void kernel_launch(void* const* d_in, const int* in_sizes, int n_in,
                              void* d_out, int out_size)
{
    const float* fea = (const float*)d_in[0];
    const float* nrm = (const float*)d_in[1];
    const float* msk = (const float*)d_in[2];
    const float* lqn = (const float*)d_in[3];
    float* out = (float*)d_out;

    QParam qp;
    int n = 0;
    for (int v = 0; v < 64; v++) {
        qp.rowstart[v] = n;
        int first = -1;
        for (int u = 0; u < 64; u++) {
            int du = 2 * u - 63, dv = 2 * v - 63;
            if (du * du + dv * dv < 1024) {
                if (first < 0) first = u;
                n++;
            }
        }
        qp.umin[v] = (first < 0) ? 0 : first;
    }
    qp.rowstart[64] = n;
    qp.nv = n;

    const int qblocks = (n + QT - 1) / QT;   // 7

    static int smem_set = 0;
    if (!smem_set) {
        cudaFuncSetAttribute(k_main, cudaFuncAttributeMaxDynamicSharedMemorySize,
                             SMEM_TOT);
        smem_set = 1;
    }

    k_prep<<<dim3(TCH, 2, BS), 256>>>(fea, nrm, msk);
    k_main<<<dim3(qblocks, NSEG, BS), 256, SMEM_TOT>>>(lqn, qp);
    k_final<<<dim3(NQ, BS), 96>>>(out, qp);
}

// round 16
// speedup vs baseline: 1.3410x; 1.0445x over previous
#include <cuda_runtime.h>
#include <cuda_fp16.h>
#include <math.h>
#include <stdint.h>

// Problem constants
#define HW     36864          // 192*192
#define CIN    64
#define BS     2
#define NQ     4096
#define COUT   69

// Tiling
#define QT     128            // queries per block
#define CK     128            // m per chunk
#define NSEG   31             // grid 7*31*2 = 434 <= 148*occ3 = 444 (single wave)
#define TCH    (HW / CK)      // 288 chunks
#define MAXV   896            // 7 * 128 slots
#define PSTR   272            // V row stride bytes (128 fp16 + 16B pad)
#define NCH    72             // V rows: 64 fea + 3 sq + 3 nrm + ones + zero
#define VROWS  72
#define VBLOB  (VROWS * PSTR) // 19584 B per chunk
#define NBLOB  1792           // pA float4[64] | pB float2[64] | pM u32[64]
#define NTILE  9              // n8 mma tiles (ch 0..71)

// dynamic smem: 3 V buffers, 3 N buffers, 3 mbarriers
#define SM_V(j)  ((j) * VBLOB)
#define SM_N(j)  (3 * VBLOB + (j) * NBLOB)
#define SM_MBAR  (3 * VBLOB + 3 * NBLOB)
#define SMEM_TOT (SM_MBAR + 64)

struct QParam {
    int nv;
    int rowstart[65];
    int umin[64];
};

// Precomputed chunk images + split-K partials
__device__ __align__(16) char  g_V[BS][TCH][VBLOB];
__device__ __align__(16) char  g_N[BS][TCH][NBLOB];
__device__ __align__(16) float g_acc[BS][NSEG][MAXV][NCH];

// ---------------- PTX helpers ----------------
#define FMA2(d, a, b, c) asm("fma.rn.f32x2 %0, %1, %2, %3;" : "=l"(d) : "l"(a), "l"(b), "l"(c))

__device__ __forceinline__ uint32_t smem_u32(const void* p) {
    uint32_t a;
    asm("{ .reg .u64 t; cvta.to.shared.u64 t, %1; cvt.u32.u64 %0, t; }"
        : "=r"(a) : "l"(p));
    return a;
}
__device__ __forceinline__ unsigned long long pk2(float lo, float hi) {
    unsigned long long r;
    asm("mov.b64 %0, {%1, %2};" : "=l"(r) : "f"(lo), "f"(hi));
    return r;
}
__device__ __forceinline__ void upk2(unsigned long long v, float& lo, float& hi) {
    asm("mov.b64 {%0, %1}, %2;" : "=f"(lo), "=f"(hi) : "l"(v));
}
__device__ __forceinline__ uint32_t cvt_f16x2(float lo, float hi) {
    uint32_t r; asm("cvt.rn.f16x2.f32 %0, %1, %2;" : "=r"(r) : "f"(hi), "f"(lo)); return r;
}
__device__ __forceinline__ uint32_t ex2_f16x2(uint32_t a) {
    uint32_t r; asm("ex2.approx.f16x2 %0, %1;" : "=r"(r) : "r"(a)); return r;
}
__device__ __forceinline__ uint32_t mul_f16x2(uint32_t a, uint32_t b) {
    uint32_t r; asm("mul.rn.f16x2 %0, %1, %2;" : "=r"(r) : "r"(a), "r"(b)); return r;
}

#define MBAR_INIT(addr, cnt) \
    asm volatile("mbarrier.init.shared.b64 [%0], %1;" :: "r"(addr), "r"(cnt) : "memory")
#define MBAR_EXPECT_TX(addr, bytes) \
    asm volatile("mbarrier.arrive.expect_tx.shared.b64 _, [%0], %1;" \
                 :: "r"(addr), "r"(bytes) : "memory")
#define MBAR_WAIT(mbar, parity) do {                                                        \
    asm volatile("{\n\t.reg .pred P1;\n\t"                                                  \
        "W%=:\n\t"                                                                          \
        "mbarrier.try_wait.parity.acquire.cta.shared::cta.b64 P1, [%0], %1, 0x989680;\n\t"  \
        "@P1 bra.uni D%=;\n\t"                                                              \
        "bra.uni W%=;\n\t"                                                                  \
        "D%=:\n\t}" :: "r"(mbar), "r"(parity) : "memory");                                  \
} while (0)
__device__ __forceinline__ void bulk_g2s(uint32_t dst, const void* src,
                                         uint32_t bytes, uint32_t mbar) {
    asm volatile("cp.async.bulk.shared::cluster.global.mbarrier::complete_tx::bytes "
                 "[%0], [%1], %2, [%3];"
                 :: "r"(dst), "l"(src), "r"(bytes), "r"(mbar) : "memory");
}

__device__ __forceinline__ void ldsm_x4(uint32_t& r0, uint32_t& r1, uint32_t& r2,
                                        uint32_t& r3, uint32_t addr) {
    asm volatile("ldmatrix.sync.aligned.m8n8.x4.shared.b16 {%0,%1,%2,%3}, [%4];"
                 : "=r"(r0), "=r"(r1), "=r"(r2), "=r"(r3) : "r"(addr));
}
__device__ __forceinline__ void ldsm_x2(uint32_t& r0, uint32_t& r1, uint32_t addr) {
    asm volatile("ldmatrix.sync.aligned.m8n8.x2.shared.b16 {%0,%1}, [%2];"
                 : "=r"(r0), "=r"(r1) : "r"(addr));
}
__device__ __forceinline__ void mma16816(float* d, const uint32_t* a,
                                         uint32_t b0, uint32_t b1) {
    asm volatile("mma.sync.aligned.m16n8k16.row.col.f32.f16.f16.f32 "
                 "{%0,%1,%2,%3}, {%4,%5,%6,%7}, {%8,%9}, {%0,%1,%2,%3};"
                 : "+f"(d[0]), "+f"(d[1]), "+f"(d[2]), "+f"(d[3])
                 : "r"(a[0]), "r"(a[1]), "r"(a[2]), "r"(a[3]), "r"(b0), "r"(b1));
}

// ---------------- query helpers ----------------
__device__ __forceinline__ bool q_valid(int u, int v) {
    int du = 2 * u - 63, dv = 2 * v - 63;
    return du * du + dv * dv < 1024;
}
__device__ __forceinline__ int slot_to_qidx(const QParam& qp, int slot) {
    if (slot >= qp.nv) return -1;
    int lo = 0, hi = 64;
    while (hi - lo > 1) {
        int mid = (lo + hi) >> 1;
        if (qp.rowstart[mid] <= slot) lo = mid; else hi = mid;
    }
    return lo * 64 + qp.umin[lo] + (slot - qp.rowstart[lo]);
}
__device__ __forceinline__ void qn_of(int qidx, float& x, float& y, float& z) {
    if (qidx < 0) { x = y = z = 0.f; return; }
    int v = qidx >> 6, u = qidx & 63;
    if (!q_valid(u, v)) { x = y = z = 0.f; return; }
    float p =  4.0f * ((u + 0.5f) * (1.0f / 64.0f) - 0.5f);
    float q = -4.0f * ((v + 0.5f) * (1.0f / 64.0f) - 0.5f);
    float r2 = p * p + q * q;
    float inv = 1.0f / (1.0f + r2);
    x = 2.0f * p * inv;
    y = 2.0f * q * inv;
    z = (1.0f - r2) * inv;
}

// -------------------------------------------------------------------------
// k_prep: build per-chunk fp16 V-tile images + packed normal/mask blobs.
// Grid (TCH, 4, BS): four CTAs per chunk (16 fea rows each + spread extras).
// -------------------------------------------------------------------------
__global__ __launch_bounds__(256)
void k_prep(const float* __restrict__ fea, const float* __restrict__ nrm,
            const float* __restrict__ msk)
{
    const int ch = blockIdx.x, quarter = blockIdx.y, b = blockIdx.z;
    const int t = threadIdx.x;
    const int mb0 = ch * CK;
    char* vdst = &g_V[b][ch][0];
    char* ndst = &g_N[b][ch][0];

    // fea rows [quarter*16, quarter*16+16) (+ squares of 61-63 -> rows 64-66)
    {
        const int vc = quarter * 16 + (t >> 4);    // 16 threads per row
        const int vq = (t & 15) * 8;               // 8 floats per thread
        const float* src = fea + ((size_t)b * CIN + vc) * HW + mb0 + vq;
        const float4 v0 = *(const float4*)(src);
        const float4 v1 = *(const float4*)(src + 4);
        uint4* d0 = (uint4*)(vdst + vc * PSTR + vq * 2);
        d0[0] = make_uint4(cvt_f16x2(v0.x, v0.y), cvt_f16x2(v0.z, v0.w),
                           cvt_f16x2(v1.x, v1.y), cvt_f16x2(v1.z, v1.w));
        if (vc >= 61) {
            uint4* d1 = (uint4*)(vdst + (vc + 3) * PSTR + vq * 2);
            d1[0] = make_uint4(cvt_f16x2(v0.x * v0.x, v0.y * v0.y),
                               cvt_f16x2(v0.z * v0.z, v0.w * v0.w),
                               cvt_f16x2(v1.x * v1.x, v1.y * v1.y),
                               cvt_f16x2(v1.z * v1.z, v1.w * v1.w));
        }
    }
    if (quarter == 0) {
        // normals: fp16 rows 67-69 + fp32 packed pA/pB
        for (int idx = t; idx < 3 * CK; idx += 256) {
            int d = idx >> 7, m = idx & 127;
            float v = nrm[((size_t)b * 3 + d) * HW + mb0 + m];
            *(__half*)(vdst + (67 + d) * PSTR + m * 2) = __float2half(v);
            int pp = m >> 1;
            if (d < 2) *(float*)(ndst + pp * 16 + d * 8 + (m & 1) * 4) = v;
            else       *(float*)(ndst + 1024 + pp * 8 + (m & 1) * 4) = v;
        }
    } else if (quarter == 1) {
        // mask -> f16x2 pairs
        if (t < CK) {
            float mk = msk[(size_t)b * HW + mb0 + t];
            *(__half*)(ndst + 1536 + (t >> 1) * 4 + (t & 1) * 2) = __float2half(mk);
        }
    } else if (quarter == 2) {
        // rows 70 (ones) / 71 (zero)
        for (int i = t; i < 2 * 68; i += 256) {
            int r = i / 68, w = i - r * 68;
            *(uint32_t*)(vdst + (70 + r) * PSTR + w * 4) = (r == 0) ? 0x3C003C00u : 0u;
        }
    }
}

// -------------------------------------------------------------------------
// k_main: grid (7, NSEG, BS), 256 threads, occ 3, single wave.
// Per 128-m chunk: ONE cp.async.bulk pair (thread 0) streams the prebuilt
// V+N images into a triple-buffered ring (mbarrier complete_tx), then fused
// wgen + mma (16 queries/warp x 72 ch, kk 0..7). One __syncthreads/chunk.
// -------------------------------------------------------------------------
__global__ __launch_bounds__(256, 3)
void k_main(const float* __restrict__ lqn, QParam qp)
{
    extern __shared__ char smem[];
    const uint32_t sb = smem_u32(smem);
    const uint32_t mb[3] = { sb + SM_MBAR, sb + SM_MBAR + 8, sb + SM_MBAR + 16 };

    const int t = threadIdx.x;
    const int wid = t >> 5, lid = t & 31;
    const int qb = blockIdx.x, seg = blockIdx.y, b = blockIdx.z;
    const int slot0 = qb * QT;

    const float scale = __expf(lqn[0]) * 0.57735026918962576f;
    const float off   = 1.0f - 4.0f / scale;           // w <= e^4, fp16-safe
    const float k2c   = scale * 1.44269504088896341f;
    const unsigned long long bb2 = pk2(-k2c * off, -k2c * off);

    // fused-A role: warp owns queries [wid*16, wid*16+16); lane rows l>>2, +8
    float qx0, qy0, qz0, qx1, qy1, qz1;
    qn_of(slot_to_qidx(qp, slot0 + wid * 16 + (lid >> 2)),     qx0, qy0, qz0);
    qn_of(slot_to_qidx(qp, slot0 + wid * 16 + (lid >> 2) + 8), qx1, qy1, qz1);
    const unsigned long long qxx[2] = { pk2(qx0 * k2c, qx0 * k2c), pk2(qx1 * k2c, qx1 * k2c) };
    const unsigned long long qyy[2] = { pk2(qy0 * k2c, qy0 * k2c), pk2(qy1 * k2c, qy1 * k2c) };
    const unsigned long long qzz[2] = { pk2(qz0 * k2c, qz0 * k2c), pk2(qz1 * k2c, qz1 * k2c) };
    const int lc = lid & 3;

    const uint32_t bOff4 = (uint32_t)((lid & 15) * PSTR + (lid >> 4) * 16);
    const uint32_t bOff2 = (uint32_t)((64 + (lid & 7)) * PSTR + ((lid >> 3) & 1) * 16);

    float acc[NTILE][4];
    #pragma unroll
    for (int j = 0; j < NTILE; j++)
        #pragma unroll
        for (int k = 0; k < 4; k++) acc[j][k] = 0.f;

    const int c0 = (seg * TCH) / NSEG;
    const int c1 = ((seg + 1) * TCH) / NSEG;

    // mbarrier init + prologue bulk copy for c0 into buffer 0
    if (t == 0) { MBAR_INIT(mb[0], 1); MBAR_INIT(mb[1], 1); MBAR_INIT(mb[2], 1); }
    __syncthreads();
    if (t == 0) {
        MBAR_EXPECT_TX(mb[0], (uint32_t)(VBLOB + NBLOB));
        bulk_g2s(sb + SM_V(0), &g_V[b][c0][0], VBLOB, mb[0]);
        bulk_g2s(sb + SM_N(0), &g_N[b][c0][0], NBLOB, mb[0]);
    }

    int ph[3] = { 0, 0, 0 };

    for (int ci = c0; ci < c1; ci++) {
        const int li = ci - c0;
        const int jv = li % 3;

        // issue TMA for ci+1 into (li+1)%3 (read last at compute(li-2): safe)
        if (ci + 1 < c1 && t == 0) {
            const int jn = (li + 1) % 3;
            MBAR_EXPECT_TX(mb[jn], (uint32_t)(VBLOB + NBLOB));
            bulk_g2s(sb + SM_V(jn), &g_V[b][ci + 1][0], VBLOB, mb[jn]);
            bulk_g2s(sb + SM_N(jn), &g_N[b][ci + 1][0], NBLOB, mb[jn]);
        }

        MBAR_WAIT(mb[jv], ph[jv]);
        ph[jv] ^= 1;
        __syncthreads();   // bounds inter-thread skew to one chunk (WAR safety)

        // ---- fused wgen + mma over 8 k-subtiles of 16 m ----
        const uint32_t vb = sb + (uint32_t)SM_V(jv);
        const char* np = smem + SM_N(jv);
        #pragma unroll
        for (int kk = 0; kk < 8; kk++) {
            uint32_t bf[4][4], bC[2];
            #pragma unroll
            for (int g = 0; g < 4; g++)
                ldsm_x4(bf[g][0], bf[g][1], bf[g][2], bf[g][3],
                        vb + bOff4 + g * 16 * PSTR + kk * 32);
            ldsm_x2(bC[0], bC[1], vb + bOff2 + kk * 32);

            uint32_t a[4];
            #pragma unroll
            for (int h = 0; h < 2; h++) {
                const int pp = 8 * kk + 4 * h + lc;
                const ulonglong2 uab = *(const ulonglong2*)(np + pp * 16);
                const unsigned long long nz2 = *(const unsigned long long*)(np + 1024 + pp * 8);
                const uint32_t mk2 = *(const uint32_t*)(np + 1536 + pp * 4);
                #pragma unroll
                for (int qi = 0; qi < 2; qi++) {
                    unsigned long long c2;
                    FMA2(c2, uab.x, qxx[qi], bb2);
                    FMA2(c2, uab.y, qyy[qi], c2);
                    FMA2(c2, nz2, qzz[qi], c2);
                    float a0, a1;
                    upk2(c2, a0, a1);
                    a[2 * h + qi] = mul_f16x2(ex2_f16x2(cvt_f16x2(a0, a1)), mk2);
                }
            }

            #pragma unroll
            for (int jj = 0; jj < 8; jj++)
                mma16816(acc[jj], a, bf[jj >> 1][jj & 1], bf[jj >> 1][(jj & 1) + 2]);
            mma16816(acc[8], a, bC[0], bC[1]);
        }
    }

    // ---- write mma partials ----
    {
        const int r0 = slot0 + wid * 16 + (lid >> 2);
        const int chb = 2 * lc;
        #pragma unroll
        for (int jj = 0; jj < NTILE; jj++) {
            int ch = 8 * jj + chb;
            *(float2*)&g_acc[b][seg][r0][ch]     = make_float2(acc[jj][0], acc[jj][1]);
            *(float2*)&g_acc[b][seg][r0 + 8][ch] = make_float2(acc[jj][2], acc[jj][3]);
        }
    }
}

// -------------------------------------------------------------------------
// Finalize: one 96-thread block per (output pixel, batch). Segment loops
// fully unrolled -> 31 independent LDGs in flight per thread.
// -------------------------------------------------------------------------
__global__ void k_final(float* __restrict__ out, QParam qp)
{
    const int qidx = blockIdx.x;
    const int b    = blockIdx.y;
    const int t    = threadIdx.x;
    const int v = qidx >> 6, u = qidx & 63;

    if (!q_valid(u, v)) {
        if (t < COUT) out[((size_t)b * COUT + t) * NQ + qidx] = 0.f;
        return;
    }
    const int slot = qp.rowstart[v] + (u - qp.umin[v]);

    __shared__ float s[NCH];

    if (t < NCH) {
        float a = 0.f;
        #pragma unroll
        for (int i = 0; i < NSEG; i++) a += g_acc[b][i][slot][t];
        s[t] = a;
    }
    __syncthreads();

    const float D = s[70] + 1e-9f;
    float x, y, z;
    qn_of(qidx, x, y, z);

    if (t < 64) {
        out[((size_t)b * COUT + 5 + t) * NQ + qidx] = s[t] / D;
    } else if (t == 64) {
        float swc = x * s[67] + y * s[68] + z * s[69];
        out[((size_t)b * COUT + 0) * NQ + qidx] = swc / D;     // rm_cos
    } else if (t == 65) {
        float var = 0.f;
        #pragma unroll
        for (int i = 0; i < 3; i++) {
            float mean = s[61 + i] / D;
            var += s[64 + i] / D - mean * mean;
        }
        out[((size_t)b * COUT + 1) * NQ + qidx] = var;
    } else if (t >= 66 && t <= 68) {
        float c = (t == 66) ? x : (t == 67) ? y : z;
        out[((size_t)b * COUT + (t - 64)) * NQ + qidx] = c;    // ch 2,3,4
    }
}

extern "C" void kernel_launch(void* const* d_in, const int* in_sizes, int n_in,
                              void* d_out, int out_size)
{
    const float* fea = (const float*)d_in[0];
    const float* nrm = (const float*)d_in[1];
    const float* msk = (const float*)d_in[2];
    const float* lqn = (const float*)d_in[3];
    float* out = (float*)d_out;

    QParam qp;
    int n = 0;
    for (int v = 0; v < 64; v++) {
        qp.rowstart[v] = n;
        int first = -1;
        for (int u = 0; u < 64; u++) {
            int du = 2 * u - 63, dv = 2 * v - 63;
            if (du * du + dv * dv < 1024) {
                if (first < 0) first = u;
                n++;
            }
        }
        qp.umin[v] = (first < 0) ? 0 : first;
    }
    qp.rowstart[64] = n;
    qp.nv = n;

    const int qblocks = (n + QT - 1) / QT;   // 7

    static int smem_set = 0;
    if (!smem_set) {
        cudaFuncSetAttribute(k_main, cudaFuncAttributeMaxDynamicSharedMemorySize,
                             SMEM_TOT);
        smem_set = 1;
    }

    k_prep<<<dim3(TCH, 4, BS), 256>>>(fea, nrm, msk);
    k_main<<<dim3(qblocks, NSEG, BS), 256, SMEM_TOT>>>(lqn, qp);
    k_final<<<dim3(NQ, BS), 96>>>(out, qp);
}

// round 17
// speedup vs baseline: 1.4958x; 1.1154x over previous
#include <cuda_runtime.h>
#include <cuda_fp16.h>
#include <math.h>
#include <stdint.h>

// Problem constants
#define HW     36864          // 192*192
#define CIN    64
#define BS     2
#define NQ     4096
#define COUT   69

// Tiling
#define QT     128            // queries per block
#define CK     128            // m per chunk
#define NSEG   31             // grid 7*31*2 = 434 <= 148*occ3 = 444 (single wave)
#define TCH    (HW / CK)      // 288 chunks
#define MAXV   896            // 7 * 128 slots
#define PSTR   272            // V row stride bytes (128 fp16 + 16B pad)
#define NCH    72             // V rows: 64 fea + 3 sq + 3 nrm + ones + zero
#define VROWS  72
#define VBLOB  (VROWS * PSTR) // 19584 B per chunk
#define NSTR   48             // Nmat row stride (32B data + 16B pad), conflict-free
#define NMAT   (CK * NSTR)    // 6144 B
#define PMASK  256            // 64 f16x2 mask pairs
#define NBLOB  (NMAT + PMASK) // 6400 B
#define NTILE  9              // n8 mma tiles (ch 0..71)

// dynamic smem: 2 V buffers, 2 N buffers, mbarriers
#define SM_V(j)  ((j) * VBLOB)
#define SM_N(j)  (2 * VBLOB + (j) * NBLOB)
#define SM_MBAR  (2 * VBLOB + 2 * NBLOB)
#define SMEM_TOT (SM_MBAR + 32)     // ~52 KB

struct QParam {
    int nv;
    int rowstart[65];
    int umin[64];
};

// Precomputed chunk images + split-K partials
__device__ __align__(16) char  g_V[BS][TCH][VBLOB];
__device__ __align__(16) char  g_N[BS][TCH][NBLOB];
__device__ __align__(16) float g_acc[BS][NSEG][MAXV][NCH];

// ---------------- PTX helpers ----------------
__device__ __forceinline__ uint32_t smem_u32(const void* p) {
    uint32_t a;
    asm("{ .reg .u64 t; cvta.to.shared.u64 t, %1; cvt.u32.u64 %0, t; }"
        : "=r"(a) : "l"(p));
    return a;
}
__device__ __forceinline__ uint32_t cvt_f16x2(float lo, float hi) {
    uint32_t r; asm("cvt.rn.f16x2.f32 %0, %1, %2;" : "=r"(r) : "f"(hi), "f"(lo)); return r;
}
__device__ __forceinline__ uint32_t ex2_f16x2(uint32_t a) {
    uint32_t r; asm("ex2.approx.f16x2 %0, %1;" : "=r"(r) : "r"(a)); return r;
}
__device__ __forceinline__ uint32_t mul_f16x2(uint32_t a, uint32_t b) {
    uint32_t r; asm("mul.rn.f16x2 %0, %1, %2;" : "=r"(r) : "r"(a), "r"(b)); return r;
}

#define MBAR_INIT(addr, cnt) \
    asm volatile("mbarrier.init.shared.b64 [%0], %1;" :: "r"(addr), "r"(cnt) : "memory")
#define MBAR_EXPECT_TX(addr, bytes) \
    asm volatile("mbarrier.arrive.expect_tx.shared.b64 _, [%0], %1;" \
                 :: "r"(addr), "r"(bytes) : "memory")
#define MBAR_WAIT(mbar, parity) do {                                                        \
    asm volatile("{\n\t.reg .pred P1;\n\t"                                                  \
        "W%=:\n\t"                                                                          \
        "mbarrier.try_wait.parity.acquire.cta.shared::cta.b64 P1, [%0], %1, 0x989680;\n\t"  \
        "@P1 bra.uni D%=;\n\t"                                                              \
        "bra.uni W%=;\n\t"                                                                  \
        "D%=:\n\t}" :: "r"(mbar), "r"(parity) : "memory");                                  \
} while (0)
__device__ __forceinline__ void bulk_g2s(uint32_t dst, const void* src,
                                         uint32_t bytes, uint32_t mbar) {
    asm volatile("cp.async.bulk.shared::cluster.global.mbarrier::complete_tx::bytes "
                 "[%0], [%1], %2, [%3];"
                 :: "r"(dst), "l"(src), "r"(bytes), "r"(mbar) : "memory");
}

__device__ __forceinline__ void ldsm_x4(uint32_t& r0, uint32_t& r1, uint32_t& r2,
                                        uint32_t& r3, uint32_t addr) {
    asm volatile("ldmatrix.sync.aligned.m8n8.x4.shared.b16 {%0,%1,%2,%3}, [%4];"
                 : "=r"(r0), "=r"(r1), "=r"(r2), "=r"(r3) : "r"(addr));
}
__device__ __forceinline__ void ldsm_x2(uint32_t& r0, uint32_t& r1, uint32_t addr) {
    asm volatile("ldmatrix.sync.aligned.m8n8.x2.shared.b16 {%0,%1}, [%2];"
                 : "=r"(r0), "=r"(r1) : "r"(addr));
}
__device__ __forceinline__ void mma16816(float* d, const uint32_t* a,
                                         uint32_t b0, uint32_t b1) {
    asm volatile("mma.sync.aligned.m16n8k16.row.col.f32.f16.f16.f32 "
                 "{%0,%1,%2,%3}, {%4,%5,%6,%7}, {%8,%9}, {%0,%1,%2,%3};"
                 : "+f"(d[0]), "+f"(d[1]), "+f"(d[2]), "+f"(d[3])
                 : "r"(a[0]), "r"(a[1]), "r"(a[2]), "r"(a[3]), "r"(b0), "r"(b1));
}

// half-pair helpers
__device__ __forceinline__ uint32_t pkh(uint16_t lo, uint16_t hi) {
    return (uint32_t)lo | ((uint32_t)hi << 16);
}
__device__ __forceinline__ void hsplit(float v, uint16_t& h, uint16_t& l) {
    __half hh = __float2half_rn(v);
    h = __half_as_ushort(hh);
    l = __half_as_ushort(__float2half_rn(v - __half2float(hh)));
}

// ---------------- query helpers ----------------
__device__ __forceinline__ bool q_valid(int u, int v) {
    int du = 2 * u - 63, dv = 2 * v - 63;
    return du * du + dv * dv < 1024;
}
__device__ __forceinline__ int slot_to_qidx(const QParam& qp, int slot) {
    if (slot >= qp.nv) return -1;
    int lo = 0, hi = 64;
    while (hi - lo > 1) {
        int mid = (lo + hi) >> 1;
        if (qp.rowstart[mid] <= slot) lo = mid; else hi = mid;
    }
    return lo * 64 + qp.umin[lo] + (slot - qp.rowstart[lo]);
}
__device__ __forceinline__ void qn_of(int qidx, float& x, float& y, float& z) {
    if (qidx < 0) { x = y = z = 0.f; return; }
    int v = qidx >> 6, u = qidx & 63;
    if (!q_valid(u, v)) { x = y = z = 0.f; return; }
    float p =  4.0f * ((u + 0.5f) * (1.0f / 64.0f) - 0.5f);
    float q = -4.0f * ((v + 0.5f) * (1.0f / 64.0f) - 0.5f);
    float r2 = p * p + q * q;
    float inv = 1.0f / (1.0f + r2);
    x = 2.0f * p * inv;
    y = 2.0f * q * inv;
    z = (1.0f - r2) * inv;
}

// -------------------------------------------------------------------------
// k_prep: per-chunk fp16 V-tile images + split-normal Nmat + mask pairs.
// Grid (TCH, 4, BS). Nmat row (per m): k-slots
//   [nxh,nxl,nxh, nyh,nyl,nyh, nzh,nzl,nzh, 1,1, 0...0]  (fp16)
// pairing with A slots [qxh,qxh,qxl, qyh,qyh,qyl, qzh,qzh,qzl, bh,bl].
// -------------------------------------------------------------------------
__global__ __launch_bounds__(256)
void k_prep(const float* __restrict__ fea, const float* __restrict__ nrm,
            const float* __restrict__ msk)
{
    const int ch = blockIdx.x, quarter = blockIdx.y, b = blockIdx.z;
    const int t = threadIdx.x;
    const int mb0 = ch * CK;
    char* vdst = &g_V[b][ch][0];
    char* ndst = &g_N[b][ch][0];

    // fea rows [quarter*16, quarter*16+16) (+ squares of 61-63 -> rows 64-66)
    {
        const int vc = quarter * 16 + (t >> 4);
        const int vq = (t & 15) * 8;
        const float* src = fea + ((size_t)b * CIN + vc) * HW + mb0 + vq;
        const float4 v0 = *(const float4*)(src);
        const float4 v1 = *(const float4*)(src + 4);
        uint4* d0 = (uint4*)(vdst + vc * PSTR + vq * 2);
        d0[0] = make_uint4(cvt_f16x2(v0.x, v0.y), cvt_f16x2(v0.z, v0.w),
                           cvt_f16x2(v1.x, v1.y), cvt_f16x2(v1.z, v1.w));
        if (vc >= 61) {
            uint4* d1 = (uint4*)(vdst + (vc + 3) * PSTR + vq * 2);
            d1[0] = make_uint4(cvt_f16x2(v0.x * v0.x, v0.y * v0.y),
                               cvt_f16x2(v0.z * v0.z, v0.w * v0.w),
                               cvt_f16x2(v1.x * v1.x, v1.y * v1.y),
                               cvt_f16x2(v1.z * v1.z, v1.w * v1.w));
        }
    }
    if (quarter == 0) {
        if (t < CK) {
            const int m = t;
            float nx = nrm[((size_t)b * 3 + 0) * HW + mb0 + m];
            float ny = nrm[((size_t)b * 3 + 1) * HW + mb0 + m];
            float nz = nrm[((size_t)b * 3 + 2) * HW + mb0 + m];
            uint16_t xh, xl, yh, yl, zh, zl;
            hsplit(nx, xh, xl);
            hsplit(ny, yh, yl);
            hsplit(nz, zh, zl);
            // V rows 67-69 (fp16 normals for swc reconstruction)
            *(uint16_t*)(vdst + 67 * PSTR + m * 2) = xh;
            *(uint16_t*)(vdst + 68 * PSTR + m * 2) = yh;
            *(uint16_t*)(vdst + 69 * PSTR + m * 2) = zh;
            // Nmat row
            const uint16_t one = 0x3C00;
            uint4* nd = (uint4*)(ndst + m * NSTR);
            nd[0] = make_uint4(pkh(xh, xl), pkh(xh, yh), pkh(yl, yh), pkh(zh, zl));
            nd[1] = make_uint4(pkh(zh, one), pkh(one, 0), 0u, 0u);
        } else {
            const int m = t - 128;   // mask -> f16x2 pairs
            float mk = msk[(size_t)b * HW + mb0 + m];
            *(uint16_t*)(ndst + NMAT + (m >> 1) * 4 + (m & 1) * 2) =
                __half_as_ushort(__float2half_rn(mk));
        }
    } else if (quarter == 2) {
        // V rows 70 (ones) / 71 (zero)
        for (int i = t; i < 2 * 68; i += 256) {
            int r = i / 68, w = i - r * 68;
            *(uint32_t*)(vdst + (70 + r) * PSTR + w * 4) = (r == 0) ? 0x3C003C00u : 0u;
        }
    }
}

// -------------------------------------------------------------------------
// k_main: grid (7, NSEG, BS), 256 threads, occ 3, single wave.
// Two-stage MMA per 128-m chunk (double-buffered TMA ring):
//   stage 1: arg = A_q (const frag, double-fp16 split) x Nmat -> fp32 d
//   bridge:  cvt -> ex2.f16x2 -> *mask  == stage-2 A fragment
//   stage 2: P x V^T (72 ch incl. sq/nrm/ones rows) in registers
// -------------------------------------------------------------------------
__global__ __launch_bounds__(256, 3)
void k_main(const float* __restrict__ lqn, QParam qp)
{
    extern __shared__ char smem[];
    const uint32_t sb = smem_u32(smem);
    const uint32_t mb[2] = { sb + SM_MBAR, sb + SM_MBAR + 8 };

    const int t = threadIdx.x;
    const int wid = t >> 5, lid = t & 31;
    const int qb = blockIdx.x, seg = blockIdx.y, b = blockIdx.z;
    const int slot0 = qb * QT;
    const int lc = lid & 3;

    const float scale = __expf(lqn[0]) * 0.57735026918962576f;
    const float off   = 1.0f - 4.0f / scale;           // w <= e^4, fp16-safe
    const float k2c   = scale * 1.44269504088896341f;
    const float bias  = -k2c * off;

    // ---- per-warp constant stage-1 A fragment (queries r, r+8) ----
    uint32_t a_q[4];
    {
        float x0, y0, z0, x1, y1, z1;
        qn_of(slot_to_qidx(qp, slot0 + wid * 16 + (lid >> 2)),     x0, y0, z0);
        qn_of(slot_to_qidx(qp, slot0 + wid * 16 + (lid >> 2) + 8), x1, y1, z1);
        uint16_t xh0, xl0, yh0, yl0, zh0, zl0, xh1, xl1, yh1, yl1, zh1, zl1, bh, bl;
        hsplit(x0 * k2c, xh0, xl0); hsplit(y0 * k2c, yh0, yl0); hsplit(z0 * k2c, zh0, zl0);
        hsplit(x1 * k2c, xh1, xl1); hsplit(y1 * k2c, yh1, yl1); hsplit(z1 * k2c, zh1, zl1);
        hsplit(bias, bh, bl);
        if (lc == 0) {
            a_q[0] = pkh(xh0, xh0); a_q[1] = pkh(xh1, xh1);
            a_q[2] = pkh(zl0, bh);  a_q[3] = pkh(zl1, bh);
        } else if (lc == 1) {
            a_q[0] = pkh(xl0, yh0); a_q[1] = pkh(xl1, yh1);
            a_q[2] = pkh(bl, 0);    a_q[3] = pkh(bl, 0);
        } else if (lc == 2) {
            a_q[0] = pkh(yh0, yl0); a_q[1] = pkh(yh1, yl1);
            a_q[2] = 0;             a_q[3] = 0;
        } else {
            a_q[0] = pkh(zh0, zh0); a_q[1] = pkh(zh1, zh1);
            a_q[2] = 0;             a_q[3] = 0;
        }
    }

    const uint32_t bOff4 = (uint32_t)((lid & 15) * PSTR + (lid >> 4) * 16);
    const uint32_t bOff2 = (uint32_t)((64 + (lid & 7)) * PSTR + ((lid >> 3) & 1) * 16);
    const uint32_t nOff  = (uint32_t)((lid & 15) * NSTR + (lid >> 4) * 16);

    float acc[NTILE][4];
    #pragma unroll
    for (int j = 0; j < NTILE; j++)
        #pragma unroll
        for (int k = 0; k < 4; k++) acc[j][k] = 0.f;

    const int c0 = (seg * TCH) / NSEG;
    const int c1 = ((seg + 1) * TCH) / NSEG;

    if (t == 0) { MBAR_INIT(mb[0], 1); MBAR_INIT(mb[1], 1); }
    __syncthreads();
    if (t == 0) {
        MBAR_EXPECT_TX(mb[0], (uint32_t)(VBLOB + NBLOB));
        bulk_g2s(sb + SM_V(0), &g_V[b][c0][0], VBLOB, mb[0]);
        bulk_g2s(sb + SM_N(0), &g_N[b][c0][0], NBLOB, mb[0]);
    }

    int ph[2] = { 0, 0 };

    for (int ci = c0; ci < c1; ci++) {
        const int li = ci - c0;
        const int jv = li & 1;

        MBAR_WAIT(mb[jv], ph[jv]);
        ph[jv] ^= 1;
        __syncthreads();   // all readers done with buffer jv^1 before refill

        if (ci + 1 < c1 && t == 0) {
            const int jn = jv ^ 1;
            MBAR_EXPECT_TX(mb[jn], (uint32_t)(VBLOB + NBLOB));
            bulk_g2s(sb + SM_V(jn), &g_V[b][ci + 1][0], VBLOB, mb[jn]);
            bulk_g2s(sb + SM_N(jn), &g_N[b][ci + 1][0], NBLOB, mb[jn]);
        }

        const uint32_t vb = sb + (uint32_t)SM_V(jv);
        const uint32_t nm = sb + (uint32_t)SM_N(jv);
        const char* mp = smem + SM_N(jv) + NMAT;

        #pragma unroll
        for (int kk = 0; kk < 8; kk++) {
            // stage-1 B (split normals) + stage-2 B (V tile) loads
            uint32_t nb[4];
            ldsm_x4(nb[0], nb[1], nb[2], nb[3], nm + (uint32_t)(kk * 16 * NSTR) + nOff);
            uint32_t bf[4][4], bC[2];
            #pragma unroll
            for (int g = 0; g < 4; g++)
                ldsm_x4(bf[g][0], bf[g][1], bf[g][2], bf[g][3],
                        vb + bOff4 + g * 16 * PSTR + kk * 32);
            ldsm_x2(bC[0], bC[1], vb + bOff2 + kk * 32);

            // stage 1: arg for 16q x 16m
            float dA[4] = {0.f, 0.f, 0.f, 0.f};
            float dB[4] = {0.f, 0.f, 0.f, 0.f};
            mma16816(dA, a_q, nb[0], nb[2]);    // m = 16kk + [0,8)
            mma16816(dB, a_q, nb[1], nb[3]);    // m = 16kk + [8,16)
            const uint32_t mkA = *(const uint32_t*)(mp + (8 * kk + lc) * 4);
            const uint32_t mkB = *(const uint32_t*)(mp + (8 * kk + 4 + lc) * 4);

            // bridge: exp + mask -> stage-2 A fragment
            uint32_t a[4];
            a[0] = mul_f16x2(ex2_f16x2(cvt_f16x2(dA[0], dA[1])), mkA);
            a[1] = mul_f16x2(ex2_f16x2(cvt_f16x2(dA[2], dA[3])), mkA);
            a[2] = mul_f16x2(ex2_f16x2(cvt_f16x2(dB[0], dB[1])), mkB);
            a[3] = mul_f16x2(ex2_f16x2(cvt_f16x2(dB[2], dB[3])), mkB);

            // stage 2: P x V^T
            #pragma unroll
            for (int jj = 0; jj < 8; jj++)
                mma16816(acc[jj], a, bf[jj >> 1][jj & 1], bf[jj >> 1][(jj & 1) + 2]);
            mma16816(acc[8], a, bC[0], bC[1]);
        }
    }

    // ---- write mma partials ----
    {
        const int r0 = slot0 + wid * 16 + (lid >> 2);
        const int chb = 2 * lc;
        #pragma unroll
        for (int jj = 0; jj < NTILE; jj++) {
            int ch = 8 * jj + chb;
            *(float2*)&g_acc[b][seg][r0][ch]     = make_float2(acc[jj][0], acc[jj][1]);
            *(float2*)&g_acc[b][seg][r0 + 8][ch] = make_float2(acc[jj][2], acc[jj][3]);
        }
    }
}

// -------------------------------------------------------------------------
// Finalize: one 96-thread block per (output pixel, batch).
// -------------------------------------------------------------------------
__global__ void k_final(float* __restrict__ out, QParam qp)
{
    const int qidx = blockIdx.x;
    const int b    = blockIdx.y;
    const int t    = threadIdx.x;
    const int v = qidx >> 6, u = qidx & 63;

    if (!q_valid(u, v)) {
        if (t < COUT) out[((size_t)b * COUT + t) * NQ + qidx] = 0.f;
        return;
    }
    const int slot = qp.rowstart[v] + (u - qp.umin[v]);

    __shared__ float s[NCH];

    if (t < NCH) {
        float a = 0.f;
        #pragma unroll
        for (int i = 0; i < NSEG; i++) a += g_acc[b][i][slot][t];
        s[t] = a;
    }
    __syncthreads();

    const float D = s[70] + 1e-9f;
    float x, y, z;
    qn_of(qidx, x, y, z);

    if (t < 64) {
        out[((size_t)b * COUT + 5 + t) * NQ + qidx] = s[t] / D;
    } else if (t == 64) {
        float swc = x * s[67] + y * s[68] + z * s[69];
        out[((size_t)b * COUT + 0) * NQ + qidx] = swc / D;     // rm_cos
    } else if (t == 65) {
        float var = 0.f;
        #pragma unroll
        for (int i = 0; i < 3; i++) {
            float mean = s[61 + i] / D;
            var += s[64 + i] / D - mean * mean;
        }
        out[((size_t)b * COUT + 1) * NQ + qidx] = var;
    } else if (t >= 66 && t <= 68) {
        float c = (t == 66) ? x : (t == 67) ? y : z;
        out[((size_t)b * COUT + (t - 64)) * NQ + qidx] = c;    // ch 2,3,4
    }
}

extern "C" void kernel_launch(void* const* d_in, const int* in_sizes, int n_in,
                              void* d_out, int out_size)
{
    const float* fea = (const float*)d_in[0];
    const float* nrm = (const float*)d_in[1];
    const float* msk = (const float*)d_in[2];
    const float* lqn = (const float*)d_in[3];
    float* out = (float*)d_out;

    QParam qp;
    int n = 0;
    for (int v = 0; v < 64; v++) {
        qp.rowstart[v] = n;
        int first = -1;
        for (int u = 0; u < 64; u++) {
            int du = 2 * u - 63, dv = 2 * v - 63;
            if (du * du + dv * dv < 1024) {
                if (first < 0) first = u;
                n++;
            }
        }
        qp.umin[v] = (first < 0) ? 0 : first;
    }
    qp.rowstart[64] = n;
    qp.nv = n;

    const int qblocks = (n + QT - 1) / QT;   // 7

    static int smem_set = 0;
    if (!smem_set) {
        cudaFuncSetAttribute(k_main, cudaFuncAttributeMaxDynamicSharedMemorySize,
                             SMEM_TOT);
        smem_set = 1;
    }

    k_prep<<<dim3(TCH, 4, BS), 256>>>(fea, nrm, msk);
    k_main<<<dim3(qblocks, NSEG, BS), 256, SMEM_TOT>>>(lqn, qp);
    k_final<<<dim3(NQ, BS), 96>>>(out, qp);
}